// round 6
// baseline (speedup 1.0000x reference)
#include <cuda_runtime.h>

// Problem constants
#define NB 16
#define NC 3
#define H 768
#define W 768
#define HS 48            // H/16
#define WS 48            // W/16
#define NPIX (HS * WS)   // 2304
#define RADIUS 8

// Downsampled features: (f0, f1, f2, |f|^2) per (b, i). 16*2304*16B = 576 KB scratch.
__device__ float4 g_feats[NB * NPIX];

// ---------------------------------------------------------------------------
// Kernel 1: 16x bilinear downsample. Half-pixel centers => src = 16*i + 7.5,
// exact 0.5/0.5 weights => average of the 2x2 pixel block at (16y+7, 16x+7).
// Scalar loads only: x0 = 16*xi + 7 is ODD, so vector loads would misalign.
// ---------------------------------------------------------------------------
__global__ void resize_feats_kernel(const float* __restrict__ img) {
    int t = blockIdx.x * blockDim.x + threadIdx.x;
    if (t >= NB * NPIX) return;
    int b = t / NPIX;
    int i = t - b * NPIX;
    int yi = i / WS;
    int xi = i - yi * WS;
    int y0 = yi * 16 + 7;
    int x0 = xi * 16 + 7;

    float f[3];
#pragma unroll
    for (int c = 0; c < 3; ++c) {
        const float* p = img + ((size_t)(b * NC + c) * H + y0) * W + x0;
        // match separable resize: average rows first, then columns
        float r0 = 0.5f * (p[0] + p[1]);
        float r1 = 0.5f * (p[W] + p[W + 1]);
        f[c] = 0.5f * (r0 + r1);
    }
    float sq = f[0] * f[0] + f[1] * f[1] + f[2] * f[2];
    g_feats[t] = make_float4(f[0], f[1], f[2], sq);
}

// ---------------------------------------------------------------------------
// Kernel 2: affinity, row-loop form with smem-resident feature table.
// Grid (144, 16): block bx handles rows i = bx, bx+144, ..., bx+15*144.
// Stride 144 == 3*WS, so xi is CONSTANT for the whole block; each thread's
// dx mask / dx^2 are block-lifetime invariants. Features live in SHARED
// memory (36 KB/block) instead of per-thread registers -> regs drop from 47
// to ~30, allowing 3 blocks/SM (54 warps, 84% occ) to keep the L1 sector
// pipe and DRAM write path full. One float4 (4 consecutive j) per thread;
// a warp writes 512 contiguous bytes per row via streaming STG.128.
// ---------------------------------------------------------------------------
__global__ void __launch_bounds__(576, 3) affinity_kernel(float* __restrict__ out) {
    __shared__ float4 s_feats[NPIX];       // 36 KB

    const int q  = threadIdx.x;            // float4 index within row, 0..575
    const int bx = blockIdx.x;             // 0..143
    const int b  = blockIdx.y;             // 0..15

    // Cooperative load of this batch's feature table into smem (4 per thread).
    const float4* __restrict__ frow = g_feats + b * NPIX;
#pragma unroll
    for (int k = 0; k < 4; ++k)
        s_feats[q + k * 576] = frow[q + k * 576];
    __syncthreads();

    const int j0  = q * 4;
    const int yj  = q / 12;                // shared by the 4 j's (4 | 48)
    const int xj0 = j0 - yj * WS;
    const int xi  = bx - (bx / WS) * WS;   // constant across all 16 rows

    // Block-lifetime invariants: dx mask and 0.02*dx^2 term.
    float sdx[4];
    bool  ok[4];
#pragma unroll
    for (int k = 0; k < 4; ++k) {
        const int dx = xi - (xj0 + k);
        ok[k]  = (dx >= -RADIUS) && (dx <= RADIUS);
        sdx[k] = 0.02f * (float)(dx * dx);
    }

    int dy = bx / WS - yj;                 // row 0's dy; +3 per iteration
    const float4 zero = make_float4(0.f, 0.f, 0.f, 0.f);
    float4* optr = (float4*)(out + (((size_t)b * NPIX + bx) * NPIX)) + q;
    const size_t ostride = (size_t)144 * (NPIX / 4);   // float4s per 144 rows

    int i = bx;
#pragma unroll 4
    for (int it = 0; it < 16; ++it) {
        float4 v = zero;
        if (dy >= -RADIUS && dy <= RADIUS) {
            const float4 fi  = s_feats[i];           // smem broadcast
            const float  sdy = 0.02f * (float)(dy * dy);
            float* vv = (float*)&v;
#pragma unroll
            for (int k = 0; k < 4; ++k) {
                if (ok[k]) {
                    const float4 fj = s_feats[j0 + k];
                    float cd = fi.w + fj.w
                             - 2.0f * (fi.x * fj.x + fi.y * fj.y + fi.z * fj.z);
                    cd = fmaxf(cd, 0.0f);
                    vv[k] = __expf(-(50.0f * cd + sdy + sdx[k]));
                }
            }
        }
        __stcs(optr, v);                   // streaming 128-bit store
        optr += ostride;
        i  += 144;
        dy += 3;
    }
}

// ---------------------------------------------------------------------------
extern "C" void kernel_launch(void* const* d_in, const int* in_sizes, int n_in,
                              void* d_out, int out_size) {
    const float* img = (const float*)d_in[0];
    float* out = (float*)d_out;

    const int nfeat = NB * NPIX;
    resize_feats_kernel<<<(nfeat + 255) / 256, 256>>>(img);

    dim3 grid(144, NB);                    // 2304 blocks, 16 rows each
    affinity_kernel<<<grid, 576>>>(out);
}